// round 14
// baseline (speedup 1.0000x reference)
#include <cuda_runtime.h>
#include <math.h>

// ModifiedChamferLoss: H=W=M=512, N=H*W=262144
// Single launch, 144 blocks x 1024 threads (~1 CTA/SM, wave-1 only).
//  - blocks 0..127 : term1. 4 independent 256-thread groups per block, one 16(w)x32(h)
//                    tile each (2 px/thread, rows +16 share dx^2). GT candidates pruned
//                    by triangle inequality. Group sync = named bar.sync (1+group, 256).
//  - blocks 128..143: term2, 32 warps each, one GT point per warp: 32x16 box scan +
//                    coverage check (s = 1/(p^4+eps') >= ~1 bounds winners to d <= U) +
//                    exact square-expansion fallback (rare).
//  - last block (persistent u64 modular ticket -> replay-safe, no init) reduces partials.

#define MPTS  512
#define NTILE 512
#define NBT1  128                 /* term1 blocks (4 tiles each) */
#define NBT2  16                  /* term2 blocks (32 GT each)   */
#define NBTOT (NBT1 + NBT2)
#define TPB   1024
#define FULLM 0xffffffffu

#define EPSF        1e-6f
#define MAXD_F      724.07733f          /* sqrt(512^2+512^2) */
#define MAXD2_F     524288.0f
#define EPS_OVER_MD 1.3810683e-9f       /* 1e-6f / 724.07733f */

typedef unsigned long long ull;

__device__ __forceinline__ ull pk2(float lo, float hi) {
    ull r; asm("mov.b64 %0, {%1, %2};" : "=l"(r) : "f"(lo), "f"(hi)); return r;
}
#define UNPK2(a, b, v) asm("mov.b64 {%0, %1}, %2;" : "=f"(a), "=f"(b) : "l"(v))
__device__ __forceinline__ ull add2(ull a, ull b) {
    ull r; asm("add.rn.f32x2 %0, %1, %2;" : "=l"(r) : "l"(a), "l"(b)); return r;
}
__device__ __forceinline__ ull mul2(ull a, ull b) {
    ull r; asm("mul.rn.f32x2 %0, %1, %2;" : "=l"(r) : "l"(a), "l"(b)); return r;
}
__device__ __forceinline__ ull fma2(ull a, ull b, ull c) {
    ull r; asm("fma.rn.f32x2 %0, %1, %2, %3;" : "=l"(r) : "l"(a), "l"(b), "l"(c)); return r;
}
#define GBAR(gid) asm volatile("bar.sync %0, 256;" :: "r"(1 + (gid)) : "memory")

__device__ float g_part_pd[NTILE];  // per-TILE partial: sum p*min_d (plain stores)
__device__ float g_part_p[NTILE];   // per-TILE partial: sum p
__device__ int   g_min2[MPTS];      // per-GT min candidate^2 (float bits), plain stores
__device__ ull   g_done;            // persistent ticket; last block via modulo

__global__ void __launch_bounds__(TPB)
chamfer_all(const float* __restrict__ prob, const float* __restrict__ gt,
            float* __restrict__ out)
{
    const int tid  = threadIdx.x;
    const int lane = tid & 31;
    const int wid  = tid >> 5;          // 0..31
    __shared__ unsigned s_last;

    if (blockIdx.x < NBT1) {
        // ========== term1: 4 groups x (16w x 32h tile) ==========
        __shared__ __align__(16) float s_cgy[4][MPTS + 4];  // negated gt, compacted
        __shared__ __align__(16) float s_cgx[4][MPTS + 4];
        __shared__ float s_wred[4][8];
        __shared__ int   s_wcA[4][8], s_wcB[4][8];
        __shared__ float r_pd[4][8], r_p[4][8];

        const int gid  = tid >> 8;            // group 0..3
        const int gtid = tid & 255;           // tid within group
        const int gwid = gtid >> 5;           // warp within group 0..7
        const int tile = (blockIdx.x << 2) + gid;   // 0..511

        const int ty0 = (tile >> 5) << 5;     // 16 tile-rows of 32 px
        const int tx0 = (tile & 31) << 4;     // 32 tile-cols of 16 px
        const float cy = (float)ty0 + 15.5f, cx = (float)tx0 + 7.5f;

        // hoist pixel loads (overlap global latency with phase A)
        const int y0i = ty0 + (gtid >> 4), x0i = tx0 + (gtid & 15);
        const int i0  = y0i * 512 + x0i;
        const float p0 = prob[i0];
        const float p1 = prob[i0 + 16 * 512];

        // phase A: 2 GT/thread via one float4 (GT 2*gtid, 2*gtid+1)
        float4 g2 = ((const float4*)gt)[gtid];
        float dyA = cy - g2.x, dxA = cx - g2.y;
        float dyB = cy - g2.z, dxB = cx - g2.w;
        float dcA2 = fmaf(dyA, dyA, dxA * dxA);
        float dcB2 = fmaf(dyB, dyB, dxB * dxB);

        unsigned mbits = __reduce_min_sync(FULLM, __float_as_uint(fminf(dcA2, dcB2)));
        if (lane == 0) s_wred[gid][gwid] = __uint_as_float(mbits);
        GBAR(gid);
        float dmin2 = s_wred[gid][0];
        #pragma unroll
        for (int w = 1; w < 8; ++w) dmin2 = fminf(dmin2, s_wred[gid][w]);
        const float thr  = sqrtf(dmin2) + 34.94f;   // 2*r_tile(17.22) + 0.5 slack
        const float thr2 = thr * thr;

        bool keepA = dcA2 <= thr2, keepB = dcB2 <= thr2;
        unsigned balA = __ballot_sync(FULLM, keepA);
        unsigned balB = __ballot_sync(FULLM, keepB);
        if (lane == 0) { s_wcA[gid][gwid] = __popc(balA); s_wcB[gid][gwid] = __popc(balB); }
        GBAR(gid);
        int baseA = 0, totA = 0, baseB = 0, totB = 0;
        #pragma unroll
        for (int w = 0; w < 8; ++w) {
            int a = s_wcA[gid][w], b = s_wcB[gid][w];
            totA += a; totB += b;
            if (w < gwid) { baseA += a; baseB += b; }
        }
        const int ncand = totA + totB;
        if (keepA) {
            int pos = baseA + __popc(balA & ((1u << lane) - 1u));
            s_cgy[gid][pos] = -g2.x; s_cgx[gid][pos] = -g2.y;
        }
        if (keepB) {
            int pos = totA + baseB + __popc(balB & ((1u << lane) - 1u));
            s_cgy[gid][pos] = -g2.z; s_cgx[gid][pos] = -g2.w;
        }
        if (gtid == 0) {   // sentinels (d^2 ~1e14, never the min) pad to multiple of 4
            #pragma unroll
            for (int q = 0; q < 4; ++q) { s_cgy[gid][ncand + q] = 1e7f; s_cgx[gid][ncand + q] = 1e7f; }
        }
        GBAR(gid);
        const int np4 = (ncand + 3) & ~3;

        // phase B: rows (y, y+16) share dx^2; 4 GT per iteration
        const ull yy0 = pk2((float)y0i, (float)y0i);
        const ull yy1 = pk2((float)(y0i + 16), (float)(y0i + 16));
        const ull xx0 = pk2((float)x0i, (float)x0i);
        const float* gyl = s_cgy[gid];
        const float* gxl = s_cgx[gid];

        float ma0 = 3.4e38f, mb0 = 3.4e38f, ma1 = 3.4e38f, mb1 = 3.4e38f;
        for (int j = 0; j < np4; j += 4) {
            ull gy01 = *(const ull*)&gyl[j];
            ull gx01 = *(const ull*)&gxl[j];
            ull gy23 = *(const ull*)&gyl[j + 2];
            ull gx23 = *(const ull*)&gxl[j + 2];
            ull dx01 = add2(gx01, xx0);
            ull dx23 = add2(gx23, xx0);
            ull xs01 = mul2(dx01, dx01);
            ull xs23 = mul2(dx23, dx23);
            {
                ull dyv = add2(gy01, yy0);
                ull d2  = fma2(dyv, dyv, xs01);
                float a, b; UNPK2(a, b, d2);
                ma0 = fminf(ma0, a); mb0 = fminf(mb0, b);
            }
            {
                ull dyv = add2(gy01, yy1);
                ull d2  = fma2(dyv, dyv, xs01);
                float a, b; UNPK2(a, b, d2);
                ma1 = fminf(ma1, a); mb1 = fminf(mb1, b);
            }
            {
                ull dyv = add2(gy23, yy0);
                ull d2  = fma2(dyv, dyv, xs23);
                float a, b; UNPK2(a, b, d2);
                ma0 = fminf(ma0, a); mb0 = fminf(mb0, b);
            }
            {
                ull dyv = add2(gy23, yy1);
                ull d2  = fma2(dyv, dyv, xs23);
                float a, b; UNPK2(a, b, d2);
                ma1 = fminf(ma1, a); mb1 = fminf(mb1, b);
            }
        }

        float v_pd = p0 * sqrtf(fminf(ma0, mb0)) + p1 * sqrtf(fminf(ma1, mb1));
        float v_p  = p0 + p1;
        #pragma unroll
        for (int o = 16; o; o >>= 1) {
            v_pd += __shfl_down_sync(FULLM, v_pd, o);
            v_p  += __shfl_down_sync(FULLM, v_p,  o);
        }
        if (lane == 0) { r_pd[gid][gwid] = v_pd; r_p[gid][gwid] = v_p; }
        GBAR(gid);
        if (gtid == 0) {
            float a = 0.0f, b = 0.0f;
            #pragma unroll
            for (int w = 0; w < 8; ++w) { a += r_pd[gid][w]; b += r_p[gid][w]; }
            g_part_pd[tile] = a;    // plain stores, no init needed
            g_part_p[tile]  = b;
        }
    } else {
        // ========== term2: one GT point per warp (32 warps), 32(w) x 16(h) box ==========
        const int j  = ((blockIdx.x - NBT1) << 5) + wid;   // 0..511
        const float gy = __ldg(&gt[2 * j]);
        const float gx = __ldg(&gt[2 * j + 1]);
        const int ry = min(max(__float2int_rn(gy), 0), 511);
        const int rx = min(max(__float2int_rn(gx), 0), 511);
        const int r0 = min(max(ry - 7, 0), 496);
        const int c0 = min(max(rx - 15, 0), 480);

        const int   col = c0 + lane;
        const float dxl = (float)col - gx;
        const float dx2 = dxl * dxl;
        float cmin2 = MAXD2_F;
        #pragma unroll                                     // 16 loads in flight
        for (int u = 0; u < 16; ++u) {
            int   r   = r0 + u;
            float p   = __ldg(&prob[r * 512 + col]);
            float dyl = (float)r - gy;
            float d2  = fmaf(dyl, dyl, dx2);
            float p2  = p * p;
            float s   = 1.0f / (p2 * p2 + EPS_OVER_MD);
            float cand = fminf((sqrtf(d2) + EPSF) * s, MAXD_F);
            cmin2 = fminf(cmin2, cand * cand);
        }
        cmin2 = __uint_as_float(__reduce_min_sync(FULLM, __float_as_uint(cmin2)));

        // coverage radius; image-edge sides cover everything beyond them
        float top = (r0 > 0)        ? (gy - (float)r0)        : 1e9f;
        float bot = (r0 + 15 < 511) ? ((float)(r0 + 15) - gy) : 1e9f;
        float lef = (c0 > 0)        ? (gx - (float)c0)        : 1e9f;
        float rig = (c0 + 31 < 511) ? ((float)(c0 + 31) - gx) : 1e9f;
        float rcov = fminf(fminf(top, bot), fminf(lef, rig));

        // cand >= d/(1+eps') -> winners lie within U*(1+eps') of the GT.
        if (cmin2 > rcov * rcov * 0.98f) {     // exact fallback (rare)
            int W   = (int)ceilf(sqrtf(cmin2) * 1.001f) + 1;
            int rr0 = max(0, ry - W), rr1 = min(511, ry + W);
            int cc0 = max(0, rx - W), cc1 = min(511, rx + W);
            for (int r = rr0; r <= rr1; ++r) {
                float dyl = (float)r - gy;
                float dy2 = dyl * dyl;
                for (int c = cc0 + lane; c <= cc1; c += 32) {
                    float p   = prob[r * 512 + c];
                    float dxe = (float)c - gx;
                    float d2  = fmaf(dxe, dxe, dy2);
                    float p2  = p * p;
                    float s   = 1.0f / (p2 * p2 + EPS_OVER_MD);
                    float cand = fminf((sqrtf(d2) + EPSF) * s, MAXD_F);
                    cmin2 = fminf(cmin2, cand * cand);
                }
            }
            cmin2 = __uint_as_float(__reduce_min_sync(FULLM, __float_as_uint(cmin2)));
        }
        if (lane == 0) g_min2[j] = __float_as_int(cmin2);   // plain store
    }

    // ========== fused finalize: last block of THIS launch reduces and writes out ==========
    __syncthreads();                       // whole CTA (all 32 warps)
    if (tid == 0) {
        __threadfence();                   // publish stores before the ticket
        ull old = atomicAdd(&g_done, 1ull);
        s_last = ((old % (ull)NBTOT) == (ull)(NBTOT - 1)) ? 1u : 0u;
    }
    __syncthreads();
    if (s_last) {
        __threadfence();                   // acquire all other blocks' stores
        float v0 = 0.0f, v1 = 0.0f, v2 = 0.0f;
        if (tid < 512) {
            v0 = sqrtf(__int_as_float(((volatile int*)g_min2)[tid]));
            v1 = ((volatile float*)g_part_pd)[tid];
            v2 = ((volatile float*)g_part_p)[tid];
        }
        #pragma unroll
        for (int o = 16; o; o >>= 1) {
            v0 += __shfl_down_sync(FULLM, v0, o);
            v1 += __shfl_down_sync(FULLM, v1, o);
            v2 += __shfl_down_sync(FULLM, v2, o);
        }
        __shared__ float rf0[32], rf1[32], rf2[32];
        if (lane == 0) { rf0[wid] = v0; rf1[wid] = v1; rf2[wid] = v2; }
        __syncthreads();
        if (tid == 0) {
            float t2 = 0.0f, spd = 0.0f, sp = 0.0f;
            #pragma unroll
            for (int w = 0; w < 32; ++w) { t2 += rf0[w]; spd += rf1[w]; sp += rf2[w]; }
            t2 *= (1.0f / (float)MPTS);
            out[0] = spd / (sp + EPSF) + t2;
        }
    }
}

extern "C" void kernel_launch(void* const* d_in, const int* in_sizes, int n_in,
                              void* d_out, int out_size)
{
    const float* prob = (const float*)d_in[0];
    const float* gt   = (const float*)d_in[1];
    (void)in_sizes; (void)n_in; (void)out_size;

    chamfer_all<<<NBTOT, TPB>>>(prob, gt, (float*)d_out);
}

// round 15
// speedup vs baseline: 1.2113x; 1.2113x over previous
#include <cuda_runtime.h>
#include <math.h>

// ModifiedChamferLoss: H=W=M=512, N=H*W=262144
// Single launch, 320 blocks x 256 threads (single wave).
//  - blocks 0..63  : term2, one GT per warp: 32x16 box scan + coverage check
//                    (s = 1/(p^4+eps') >= ~1 bounds winners to d <= U) + exact fallback.
//  - blocks 64..319: term1, one 32x32 pixel tile (4 px/thread: 4 consecutive rows share
//                    one dx^2). GT candidates pruned by triangle inequality.
//  - last block (persistent u64 modular ticket -> replay-safe, no init) reduces partials.

#define MPTS  512
#define NB2B  64
#define NB1   256
#define NBTOT (NB2B + NB1)
#define TPB   256
#define FULLM 0xffffffffu

#define EPSF        1e-6f
#define MAXD_F      724.07733f          /* sqrt(512^2+512^2) */
#define MAXD2_F     524288.0f
#define EPS_OVER_MD 1.3810683e-9f       /* 1e-6f / 724.07733f */

typedef unsigned long long ull;

__device__ __forceinline__ ull pk2(float lo, float hi) {
    ull r; asm("mov.b64 %0, {%1, %2};" : "=l"(r) : "f"(lo), "f"(hi)); return r;
}
#define UNPK2(a, b, v) asm("mov.b64 {%0, %1}, %2;" : "=f"(a), "=f"(b) : "l"(v))
__device__ __forceinline__ ull add2(ull a, ull b) {
    ull r; asm("add.rn.f32x2 %0, %1, %2;" : "=l"(r) : "l"(a), "l"(b)); return r;
}
__device__ __forceinline__ ull mul2(ull a, ull b) {
    ull r; asm("mul.rn.f32x2 %0, %1, %2;" : "=l"(r) : "l"(a), "l"(b)); return r;
}
__device__ __forceinline__ ull fma2(ull a, ull b, ull c) {
    ull r; asm("fma.rn.f32x2 %0, %1, %2, %3;" : "=l"(r) : "l"(a), "l"(b), "l"(c)); return r;
}

__device__ float g_part_pd[NB1];   // per-tile partial: sum p*min_d (plain stores)
__device__ float g_part_p[NB1];    // per-tile partial: sum p
__device__ int   g_min2[MPTS];     // per-GT min candidate^2 (float bits), plain stores
__device__ ull   g_done;           // persistent ticket; last block via modulo

__global__ void __launch_bounds__(TPB)
chamfer_all(const float* __restrict__ prob, const float* __restrict__ gt,
            float* __restrict__ out)
{
    const int tid  = threadIdx.x;
    const int lane = tid & 31;
    const int wid  = tid >> 5;
    __shared__ unsigned s_last;

    if (blockIdx.x < NB2B) {
        // ========== term2: one GT point per warp, 32(w) x 16(h) box ==========
        const int j  = (blockIdx.x << 3) + wid;            // 0..511
        const float gy = __ldg(&gt[2 * j]);
        const float gx = __ldg(&gt[2 * j + 1]);
        const int ry = min(max(__float2int_rn(gy), 0), 511);
        const int rx = min(max(__float2int_rn(gx), 0), 511);
        const int r0 = min(max(ry - 7, 0), 496);
        const int c0 = min(max(rx - 15, 0), 480);

        const int   col = c0 + lane;
        const float dxl = (float)col - gx;
        const float dx2 = dxl * dxl;
        float cmin2 = MAXD2_F;
        #pragma unroll                                     // 16 loads in flight
        for (int u = 0; u < 16; ++u) {
            int   r   = r0 + u;
            float p   = __ldg(&prob[r * 512 + col]);
            float dyl = (float)r - gy;
            float d2  = fmaf(dyl, dyl, dx2);
            float p2  = p * p;
            float s   = 1.0f / (p2 * p2 + EPS_OVER_MD);
            float cand = fminf((sqrtf(d2) + EPSF) * s, MAXD_F);
            cmin2 = fminf(cmin2, cand * cand);
        }
        cmin2 = __uint_as_float(__reduce_min_sync(FULLM, __float_as_uint(cmin2)));

        float top = (r0 > 0)        ? (gy - (float)r0)        : 1e9f;
        float bot = (r0 + 15 < 511) ? ((float)(r0 + 15) - gy) : 1e9f;
        float lef = (c0 > 0)        ? (gx - (float)c0)        : 1e9f;
        float rig = (c0 + 31 < 511) ? ((float)(c0 + 31) - gx) : 1e9f;
        float rcov = fminf(fminf(top, bot), fminf(lef, rig));

        if (cmin2 > rcov * rcov * 0.98f) {     // exact fallback (rare)
            int W   = (int)ceilf(sqrtf(cmin2) * 1.001f) + 1;
            int rr0 = max(0, ry - W), rr1 = min(511, ry + W);
            int cc0 = max(0, rx - W), cc1 = min(511, rx + W);
            for (int r = rr0; r <= rr1; ++r) {
                float dyl = (float)r - gy;
                float dy2 = dyl * dyl;
                for (int c = cc0 + lane; c <= cc1; c += 32) {
                    float p   = prob[r * 512 + c];
                    float dxe = (float)c - gx;
                    float d2  = fmaf(dxe, dxe, dy2);
                    float p2  = p * p;
                    float s   = 1.0f / (p2 * p2 + EPS_OVER_MD);
                    float cand = fminf((sqrtf(d2) + EPSF) * s, MAXD_F);
                    cmin2 = fminf(cmin2, cand * cand);
                }
            }
            cmin2 = __uint_as_float(__reduce_min_sync(FULLM, __float_as_uint(cmin2)));
        }
        if (lane == 0) g_min2[j] = __float_as_int(cmin2);   // plain store
    } else {
        // ========== term1: 32x32 tile, 4 px/thread (4 consecutive rows share dx^2) ==========
        __shared__ __align__(16) float s_cgy[MPTS + 4];   // negated gt, compacted (+sentinels)
        __shared__ __align__(16) float s_cgx[MPTS + 4];
        __shared__ float s_wred[8];
        __shared__ int   s_wcA[8], s_wcB[8];
        __shared__ float r_pd[8], r_p[8];

        const int b1  = blockIdx.x - NB2B;                // 0..255
        const int ty0 = (b1 >> 4) << 5;                   // 16x16 grid of 32x32 tiles
        const int tx0 = (b1 & 15) << 5;
        const float cy = (float)ty0 + 15.5f, cx = (float)tx0 + 15.5f;

        // pixels: warp w owns rows [ty0+4w, +4), col = tx0+lane. Hoisted loads.
        const int x0i  = tx0 + lane;
        const int row0 = ty0 + (wid << 2);
        const int ib   = row0 * 512 + x0i;
        const float p0 = prob[ib];
        const float p1 = prob[ib + 512];
        const float p2 = prob[ib + 1024];
        const float p3 = prob[ib + 1536];

        // phase A: 2 GT/thread via one float4. r_tile = 21.92 -> thr = dmin + 44.35
        float4 g2 = ((const float4*)gt)[tid];
        float dyA = cy - g2.x, dxA = cx - g2.y;
        float dyB = cy - g2.z, dxB = cx - g2.w;
        float dcA2 = fmaf(dyA, dyA, dxA * dxA);
        float dcB2 = fmaf(dyB, dyB, dxB * dxB);

        unsigned mbits = __reduce_min_sync(FULLM, __float_as_uint(fminf(dcA2, dcB2)));
        if (lane == 0) s_wred[wid] = __uint_as_float(mbits);
        __syncthreads();
        float dmin2 = s_wred[0];
        #pragma unroll
        for (int w = 1; w < 8; ++w) dmin2 = fminf(dmin2, s_wred[w]);
        const float thr  = sqrtf(dmin2) + 44.35f;   // 2*21.92 + 0.5 slack
        const float thr2 = thr * thr;

        bool keepA = dcA2 <= thr2, keepB = dcB2 <= thr2;
        unsigned balA = __ballot_sync(FULLM, keepA);
        unsigned balB = __ballot_sync(FULLM, keepB);
        if (lane == 0) { s_wcA[wid] = __popc(balA); s_wcB[wid] = __popc(balB); }
        __syncthreads();
        int baseA = 0, totA = 0, baseB = 0, totB = 0;
        #pragma unroll
        for (int w = 0; w < 8; ++w) {
            int a = s_wcA[w], b = s_wcB[w];
            totA += a; totB += b;
            if (w < wid) { baseA += a; baseB += b; }
        }
        const int ncand = totA + totB;
        if (keepA) {
            int pos = baseA + __popc(balA & ((1u << lane) - 1u));
            s_cgy[pos] = -g2.x; s_cgx[pos] = -g2.y;
        }
        if (keepB) {
            int pos = totA + baseB + __popc(balB & ((1u << lane) - 1u));
            s_cgy[pos] = -g2.z; s_cgx[pos] = -g2.w;
        }
        if (tid == 0) {   // sentinels (d^2 ~1e14, never the min) pad to multiple of 4
            #pragma unroll
            for (int q = 0; q < 4; ++q) { s_cgy[ncand + q] = 1e7f; s_cgx[ncand + q] = 1e7f; }
        }
        __syncthreads();
        const int np4 = (ncand + 3) & ~3;

        // phase B: 4 rows share dx^2; 4 GT (2 packed pairs) per iteration
        const ull rr0v = pk2((float)row0, (float)row0);
        const ull rr1v = pk2((float)(row0 + 1), (float)(row0 + 1));
        const ull rr2v = pk2((float)(row0 + 2), (float)(row0 + 2));
        const ull rr3v = pk2((float)(row0 + 3), (float)(row0 + 3));
        const ull xx0  = pk2((float)x0i, (float)x0i);

        float m0a = 3.4e38f, m0b = 3.4e38f, m1a = 3.4e38f, m1b = 3.4e38f;
        float m2a = 3.4e38f, m2b = 3.4e38f, m3a = 3.4e38f, m3b = 3.4e38f;
        for (int j = 0; j < np4; j += 4) {
            ull gy01 = *(const ull*)&s_cgy[j];
            ull gx01 = *(const ull*)&s_cgx[j];
            ull gy23 = *(const ull*)&s_cgy[j + 2];
            ull gx23 = *(const ull*)&s_cgx[j + 2];
            ull dx01 = add2(gx01, xx0);
            ull dx23 = add2(gx23, xx0);
            ull xs01 = mul2(dx01, dx01);
            ull xs23 = mul2(dx23, dx23);
            float a, b;
            {
                ull dy = add2(gy01, rr0v); ull d2 = fma2(dy, dy, xs01);
                UNPK2(a, b, d2); m0a = fminf(m0a, a); m0b = fminf(m0b, b);
                dy = add2(gy23, rr0v); d2 = fma2(dy, dy, xs23);
                UNPK2(a, b, d2); m0a = fminf(m0a, a); m0b = fminf(m0b, b);
            }
            {
                ull dy = add2(gy01, rr1v); ull d2 = fma2(dy, dy, xs01);
                UNPK2(a, b, d2); m1a = fminf(m1a, a); m1b = fminf(m1b, b);
                dy = add2(gy23, rr1v); d2 = fma2(dy, dy, xs23);
                UNPK2(a, b, d2); m1a = fminf(m1a, a); m1b = fminf(m1b, b);
            }
            {
                ull dy = add2(gy01, rr2v); ull d2 = fma2(dy, dy, xs01);
                UNPK2(a, b, d2); m2a = fminf(m2a, a); m2b = fminf(m2b, b);
                dy = add2(gy23, rr2v); d2 = fma2(dy, dy, xs23);
                UNPK2(a, b, d2); m2a = fminf(m2a, a); m2b = fminf(m2b, b);
            }
            {
                ull dy = add2(gy01, rr3v); ull d2 = fma2(dy, dy, xs01);
                UNPK2(a, b, d2); m3a = fminf(m3a, a); m3b = fminf(m3b, b);
                dy = add2(gy23, rr3v); d2 = fma2(dy, dy, xs23);
                UNPK2(a, b, d2); m3a = fminf(m3a, a); m3b = fminf(m3b, b);
            }
        }

        float v_pd = p0 * sqrtf(fminf(m0a, m0b)) + p1 * sqrtf(fminf(m1a, m1b))
                   + p2 * sqrtf(fminf(m2a, m2b)) + p3 * sqrtf(fminf(m3a, m3b));
        float v_p  = (p0 + p1) + (p2 + p3);
        #pragma unroll
        for (int o = 16; o; o >>= 1) {
            v_pd += __shfl_down_sync(FULLM, v_pd, o);
            v_p  += __shfl_down_sync(FULLM, v_p,  o);
        }
        if (lane == 0) { r_pd[wid] = v_pd; r_p[wid] = v_p; }
        __syncthreads();
        if (tid == 0) {
            float a = 0.0f, b = 0.0f;
            #pragma unroll
            for (int w = 0; w < 8; ++w) { a += r_pd[w]; b += r_p[w]; }
            g_part_pd[b1] = a;      // plain stores, no init needed
            g_part_p[b1]  = b;
        }
    }

    // ========== fused finalize: last block of THIS launch reduces and writes out ==========
    __syncthreads();
    if (tid == 0) {
        __threadfence();                       // publish stores before the ticket
        ull old = atomicAdd(&g_done, 1ull);
        s_last = ((old % (ull)NBTOT) == (ull)(NBTOT - 1)) ? 1u : 0u;
    }
    __syncthreads();
    if (s_last) {
        __threadfence();                       // acquire all other blocks' stores
        float v0 = sqrtf(__int_as_float(((volatile int*)g_min2)[tid]))
                 + sqrtf(__int_as_float(((volatile int*)g_min2)[tid + 256]));
        float v1 = ((volatile float*)g_part_pd)[tid];
        float v2 = ((volatile float*)g_part_p)[tid];
        #pragma unroll
        for (int o = 16; o; o >>= 1) {
            v0 += __shfl_down_sync(FULLM, v0, o);
            v1 += __shfl_down_sync(FULLM, v1, o);
            v2 += __shfl_down_sync(FULLM, v2, o);
        }
        __shared__ float rf0[8], rf1[8], rf2[8];
        if (lane == 0) { rf0[wid] = v0; rf1[wid] = v1; rf2[wid] = v2; }
        __syncthreads();
        if (tid == 0) {
            float t2 = 0.0f, spd = 0.0f, sp = 0.0f;
            #pragma unroll
            for (int w = 0; w < 8; ++w) { t2 += rf0[w]; spd += rf1[w]; sp += rf2[w]; }
            t2 *= (1.0f / (float)MPTS);
            out[0] = spd / (sp + EPSF) + t2;
        }
    }
}

extern "C" void kernel_launch(void* const* d_in, const int* in_sizes, int n_in,
                              void* d_out, int out_size)
{
    const float* prob = (const float*)d_in[0];
    const float* gt   = (const float*)d_in[1];
    (void)in_sizes; (void)n_in; (void)out_size;

    chamfer_all<<<NBTOT, TPB>>>(prob, gt, (float*)d_out);
}